// round 14
// baseline (speedup 1.0000x reference)
#include <cuda_runtime.h>
#include <cuda_fp16.h>
#include <cstdint>

#define NN 50000
#define NE 600000
#define HH 128
#define NG 128
#define NC 10
#define NT64 782                    // ceil(50000/64)
#define GEMM_GRID 296               // 2 CTAs per SM, persistent

// ---------------- tile geometry ----------------------------------------------
#define TSTRIDE 272                 // 128 fp16 (256B) + 16B pad -> ldmatrix conflict-free
#define TILE_B  (128 * TSTRIDE)     // 34816 bytes per 128x128 fp16 image

// ---------------- scratch (static device globals; no allocation) ------------
__device__ __half g_h0[NN*HH];     // W-path output ping (fp16)
__device__ __half g_h1[NN*HH];     // W-path output pong
__device__ __half g_f [NN*HH];     // skip-path (X@R+b) values, fp16, in-place
__device__ uint2 g_edge[NE];       // packed {src, bits(w)} CSR records
__device__ int   g_deg [NN];
__device__ int   g_beg [NN];       // after k_fill: END of each segment
__device__ int   g_total;
__device__ float g_dinv[NN];
__device__ float g_pool[NG*HH];
__device__ float g_cnt [NG];
// fp16 weight images: [layer][W,R][TILE_B] -- W,R contiguous per layer
__device__ __align__(16) char g_wimg[4][2][TILE_B];

__device__ __forceinline__ __half* selH(int s) { return s ? g_h1 : g_h0; }

__device__ __forceinline__ uint32_t s2u(const void* p) {
    uint32_t a;
    asm("{ .reg .u64 t; cvta.to.shared.u64 t, %1; cvt.u32.u64 %0, t; }"
        : "=r"(a) : "l"(p));
    return a;
}

// ---------------- GEMM SMEM layout (per CTA: 87040 B -> 2 CTA/SM) -----------
#define A16  0
#define BW16 17408                  // W image
#define BR16 (17408 + TILE_B)       // R image
#define SM2_TOTAL (17408 + 2 * TILE_B)   // 87040

__device__ __forceinline__ void ldm4(uint32_t* r, uint32_t addr) {
    asm volatile("ldmatrix.sync.aligned.m8n8.x4.shared.b16 {%0,%1,%2,%3}, [%4];"
                 : "=r"(r[0]), "=r"(r[1]), "=r"(r[2]), "=r"(r[3]) : "r"(addr));
}
__device__ __forceinline__ void mma16816h(float* c, const uint32_t* a,
                                          uint32_t b0, uint32_t b1) {
    asm volatile(
        "mma.sync.aligned.m16n8k16.row.col.f32.f16.f16.f32 "
        "{%0,%1,%2,%3}, {%4,%5,%6,%7}, {%8,%9}, {%0,%1,%2,%3};"
        : "+f"(c[0]), "+f"(c[1]), "+f"(c[2]), "+f"(c[3])
        : "r"(a[0]), "r"(a[1]), "r"(a[2]), "r"(a[3]), "r"(b0), "r"(b1));
}

__device__ __forceinline__ uint32_t packh2(float a, float b) {
    __half2 h = __floats2half2_rn(a, b);
    return *(uint32_t*)&h;
}

// gather-sum for one node row (4 fp16 cols per lane), fp32 accum
__device__ __forceinline__ float4 agg_row(int i, const __half* __restrict__ hIn,
                                          int laneOff) {
    uint2 u = *(const uint2*)(g_f + i * HH + laneOff);
    float2 ia = __half22float2(*(__half2*)&u.x), ib = __half22float2(*(__half2*)&u.y);
    float4 acc = make_float4(ia.x, ia.y, ib.x, ib.y);
    const int end = g_beg[i];
    int e = end - g_deg[i];
    for (; e + 4 <= end; e += 4) {
        uint2 e0 = g_edge[e],   e1 = g_edge[e+1];
        uint2 e2 = g_edge[e+2], e3 = g_edge[e+3];
        float w0 = __uint_as_float(e0.y), w1 = __uint_as_float(e1.y);
        float w2 = __uint_as_float(e2.y), w3 = __uint_as_float(e3.y);
        uint2 u0 = *(const uint2*)(hIn + e0.x * HH + laneOff);
        uint2 u1 = *(const uint2*)(hIn + e1.x * HH + laneOff);
        uint2 u2 = *(const uint2*)(hIn + e2.x * HH + laneOff);
        uint2 u3 = *(const uint2*)(hIn + e3.x * HH + laneOff);
        float2 a0 = __half22float2(*(__half2*)&u0.x), b0 = __half22float2(*(__half2*)&u0.y);
        float2 a1 = __half22float2(*(__half2*)&u1.x), b1 = __half22float2(*(__half2*)&u1.y);
        float2 a2 = __half22float2(*(__half2*)&u2.x), b2 = __half22float2(*(__half2*)&u2.y);
        float2 a3 = __half22float2(*(__half2*)&u3.x), b3 = __half22float2(*(__half2*)&u3.y);
        acc.x += a0.x*w0 + a1.x*w1 + a2.x*w2 + a3.x*w3;
        acc.y += a0.y*w0 + a1.y*w1 + a2.y*w2 + a3.y*w3;
        acc.z += b0.x*w0 + b1.x*w1 + b2.x*w2 + b3.x*w3;
        acc.w += b0.y*w0 + b1.y*w1 + b2.y*w2 + b3.y*w3;
    }
    for (; e < end; e++) {
        uint2 ed = g_edge[e];
        float w = __uint_as_float(ed.y);
        uint2 uu = *(const uint2*)(hIn + ed.x * HH + laneOff);
        float2 a = __half22float2(*(__half2*)&uu.x), b = __half22float2(*(__half2*)&uu.y);
        acc.x += a.x * w; acc.y += a.y * w;
        acc.z += b.x * w; acc.w += b.y * w;
    }
    acc.x = fmaxf(acc.x, 0.f); acc.y = fmaxf(acc.y, 0.f);
    acc.z = fmaxf(acc.z, 0.f); acc.w = fmaxf(acc.w, 0.f);
    return acc;
}

// ---------------- fused: zero scratch + fp16 weight images ------------------
__global__ void k_pre(const float* __restrict__ W1, const float* __restrict__ R1,
                      const float* __restrict__ Wc, const float* __restrict__ Rc) {
    if (blockIdx.x < 196) {
        int i = blockIdx.x * 256 + threadIdx.x;
        if (i < NN) g_deg[i] = 0;
        if (i < NG*HH) g_pool[i] = 0.f;
        if (i < NG) g_cnt[i] = 0.f;
        if (i == 0) g_total = 0;
        return;
    }
    const int b = blockIdx.x - 196;
    const int layer = b >> 1;
    const int isR = b & 1;
    const float* src;
    if (layer == 0) src = isR ? R1 : W1;
    else src = (isR ? Rc : Wc) + (layer - 1) * HH * HH;
    char* img = g_wimg[layer][isR];
    for (int idx = threadIdx.x; idx < HH * HH; idx += 256) {
        int n = idx >> 7, k = idx & 127;
        __half h = __float2half(src[k * HH + n]);   // transpose [k][n] -> [n][k]
        *(unsigned short*)(img + n * TSTRIDE + k * 2) = *(unsigned short*)&h;
    }
}

// ---------------- shared GEMM core (A already in SMEM) -----------------------
struct WarpCtx {
    uint32_t aOff, bOff;
    int n0, wm, gq, t4;
};

__device__ __forceinline__ void gemm_core_and_epilogue(
    const uint32_t sbase, const WarpCtx& W, int row0,
    __half* hOut, const float* bx, const float* by)
{
    const uint32_t aB = sbase + A16;
    const uint32_t bWB = sbase + BW16, bRB = sbase + BR16;
    float cW[2][4][4], cR[2][4][4];
#pragma unroll
    for (int i = 0; i < 2; i++)
#pragma unroll
        for (int j = 0; j < 4; j++)
#pragma unroll
            for (int z = 0; z < 4; z++) { cW[i][j][z] = 0.f; cR[i][j][z] = 0.f; }

#pragma unroll 1
    for (int k0 = 0; k0 < 128; k0 += 16) {
        const uint32_t kB = (uint32_t)(k0 * 2);
        uint32_t a[2][4];
#pragma unroll
        for (int mf = 0; mf < 2; mf++)
            ldm4(a[mf], aB + W.aOff + mf * (16 * TSTRIDE) + kB);
#pragma unroll
        for (int nf2 = 0; nf2 < 2; nf2++) {
            uint32_t bb[4];
            ldm4(bb, bWB + W.bOff + nf2 * (16 * TSTRIDE) + kB);
#pragma unroll
            for (int mf = 0; mf < 2; mf++) {
                mma16816h(cW[mf][nf2 * 2],     a[mf], bb[0], bb[1]);
                mma16816h(cW[mf][nf2 * 2 + 1], a[mf], bb[2], bb[3]);
            }
            ldm4(bb, bRB + W.bOff + nf2 * (16 * TSTRIDE) + kB);
#pragma unroll
            for (int mf = 0; mf < 2; mf++) {
                mma16816h(cR[mf][nf2 * 2],     a[mf], bb[0], bb[1]);
                mma16816h(cR[mf][nf2 * 2 + 1], a[mf], bb[2], bb[3]);
            }
        }
    }
#pragma unroll
    for (int nf = 0; nf < 4; nf++) {
        const int col = W.n0 + nf * 8 + 2 * W.t4;
#pragma unroll
        for (int mf = 0; mf < 2; mf++) {
            int rlo = row0 + W.wm * 32 + mf * 16 + W.gq;
            if (rlo < NN) {
                *(__half2*)(hOut + rlo * 128 + col) =
                    __floats2half2_rn(cW[mf][nf][0], cW[mf][nf][1]);
                *(__half2*)(g_f + rlo * 128 + col) =
                    __floats2half2_rn(cR[mf][nf][0] + bx[nf], cR[mf][nf][1] + by[nf]);
            }
            if (rlo + 8 < NN) {
                *(__half2*)(hOut + (rlo + 8) * 128 + col) =
                    __floats2half2_rn(cW[mf][nf][2], cW[mf][nf][3]);
                *(__half2*)(g_f + (rlo + 8) * 128 + col) =
                    __floats2half2_rn(cR[mf][nf][2] + bx[nf], cR[mf][nf][3] + by[nf]);
            }
        }
    }
}

__device__ __forceinline__ WarpCtx make_ctx(int tid) {
    WarpCtx W;
    const int wid = tid >> 5, lane = tid & 31;
    const int wm = wid & 1, wn = wid >> 1;
    W.wm = wm;
    W.n0 = wn * 32;
    W.aOff = (uint32_t)((wm * 32 + (lane & 15)) * TSTRIDE + (lane >> 4) * 16);
    const int q = lane >> 3, r8 = lane & 7;
    W.bOff = (uint32_t)((W.n0 + ((q & 2) << 2) + r8) * TSTRIDE + (q & 1) * 16);
    W.gq = lane >> 2;
    W.t4 = lane & 3;
    return W;
}

__device__ __forceinline__ void load_B_images(char* smem, int tid, int layer) {
    const float4* src = (const float4*)g_wimg[layer][0];
    float4* d4 = (float4*)(smem + BW16);
#pragma unroll
    for (int it = 0; it < 17; it++)
        d4[it * 256 + tid] = src[it * 256 + tid];
}

__device__ __forceinline__ void load_bias(const float* bias, const WarpCtx& W,
                                          float* bx, float* by) {
#pragma unroll
    for (int nf = 0; nf < 4; nf++) {
        float2 bv = *(const float2*)(bias + W.n0 + nf * 8 + 2 * W.t4);
        bx[nf] = bv.x; by[nf] = bv.y;
    }
}

// ---------------- layer 0 GEMM: fp32 x -> g_h0 + g_f -------------------------
__global__ void __launch_bounds__(256, 2) k_gemm0(
    const float* __restrict__ Xext, const float* __restrict__ bias)
{
    extern __shared__ char smem[];
    const uint32_t sbase = s2u(smem);
    const int tid = threadIdx.x;
    load_B_images(smem, tid, 0);
    WarpCtx W = make_ctx(tid);
    float bx[4], by[4];
    load_bias(bias, W, bx, by);

    const int lm = tid >> 5;
    const int lc4 = (tid & 31) * 4;

    for (int tile = blockIdx.x; tile < NT64; tile += GEMM_GRID) {
        const int row0 = tile * 64;
        __syncthreads();
#pragma unroll
        for (int it = 0; it < 8; it++) {
            int gr = row0 + lm + it * 8;
            float4 w = (gr < NN) ? *(const float4*)(Xext + gr * 128 + lc4)
                                 : make_float4(0.f, 0.f, 0.f, 0.f);
            uint32_t bo = (lm + it * 8) * TSTRIDE + lc4 * 2;
            *(uint32_t*)(smem + A16 + bo)     = packh2(w.x, w.y);
            *(uint32_t*)(smem + A16 + bo + 4) = packh2(w.z, w.w);
        }
        __syncthreads();
        gemm_core_and_epilogue(sbase, W, row0, g_h0, bx, by);
    }
}

// ---------------- fused agg + GEMM for layers 1..3 ---------------------------
// agg(prev layer) -> SMEM A (relu'd fp16) -> GEMM -> hOut + g_f (in place)
__global__ void __launch_bounds__(256, 2) k_fused(
    int hIn, int hOut_sel, int layer, const float* __restrict__ bias)
{
    extern __shared__ char smem[];
    const uint32_t sbase = s2u(smem);
    const int tid = threadIdx.x;
    const int wid = tid >> 5, lane = tid & 31;
    const __half* hIn_p = selH(hIn);
    __half* hOut_p = selH(hOut_sel);
    load_B_images(smem, tid, layer);
    WarpCtx W = make_ctx(tid);
    float bx[4], by[4];
    load_bias(bias, W, bx, by);

    const int laneOff = lane * 4;

    for (int tile = blockIdx.x; tile < NT64; tile += GEMM_GRID) {
        const int row0 = tile * 64;
        __syncthreads();   // SMEM A free of previous tile's readers
        // ---- agg phase: warp handles 8 rows -> SMEM A ----
#pragma unroll 1
        for (int r = 0; r < 8; r++) {
            const int m = wid * 8 + r;
            const int i = row0 + m;
            float4 acc = make_float4(0.f, 0.f, 0.f, 0.f);
            if (i < NN) acc = agg_row(i, hIn_p, laneOff);
            uint2 o;
            *(__half2*)&o.x = __floats2half2_rn(acc.x, acc.y);
            *(__half2*)&o.y = __floats2half2_rn(acc.z, acc.w);
            *(uint2*)(smem + A16 + m * TSTRIDE + laneOff * 2) = o;
        }
        __syncthreads();
        gemm_core_and_epilogue(sbase, W, row0, hOut_p, bx, by);
    }
}

// ---------------- graph preprocessing --------------------------------------
__global__ void k_deg(const int* __restrict__ ei) {
    int e = blockIdx.x * blockDim.x + threadIdx.x;
    if (e < NE) {
        int d = ei[NE + e];
        if (d >= 0 && d < NN) atomicAdd(&g_deg[d], 1);
    }
}

__global__ void k_off() {
    __shared__ int sh[256];
    __shared__ int base;
    const int t = threadIdx.x;
    const int i = blockIdx.x * 256 + t;
    int d = (i < NN) ? g_deg[i] : 0;
    if (i < NN) g_dinv[i] = (d > 0) ? rsqrtf((float)d) : 0.f;
    sh[t] = d;
    __syncthreads();
    for (int off = 1; off < 256; off <<= 1) {
        int v = (t >= off) ? sh[t - off] : 0;
        __syncthreads();
        sh[t] += v;
        __syncthreads();
    }
    if (t == 255) base = atomicAdd(&g_total, sh[255]);
    __syncthreads();
    if (i < NN) g_beg[i] = base + sh[t] - d;
}

__global__ void k_fill(const int* __restrict__ ei) {
    int e = blockIdx.x * blockDim.x + threadIdx.x;
    if (e < NE) {
        int s = ei[e];
        int d = ei[NE + e];
        if (s < 0 || s >= NN || d < 0 || d >= NN) return;
        float w = g_dinv[s] * g_dinv[d];
        int pos = atomicAdd(&g_beg[d], 1);
        g_edge[pos] = make_uint2((uint32_t)s, __float_as_uint(w));
    }
}

// ---------------- final aggregation -> fp32 lastOut --------------------------
__global__ void k_aggF(int hIn, float* __restrict__ lastOut) {
    const __half* hIn_p = selH(hIn);
    const int wid = threadIdx.x >> 5, lane = threadIdx.x & 31;
    const int i = blockIdx.x * 4 + wid;
    if (i >= NN) return;
    float4 acc = agg_row(i, hIn_p, lane * 4);
    *(float4*)(lastOut + i * HH + lane * 4) = acc;
}

// ---------------- mean-pool accumulation (input already relu'd) -------------
__global__ void k_pool(const float* __restrict__ f,
                       const int* __restrict__ batch) {
    const int t = threadIdx.x;
    const int base = blockIdx.x * 64;
    float acc = 0.f;
    int cur = -1;
    for (int r = 0; r < 64; r++) {
        int i = base + r;
        if (i >= NN) break;
        float v = f[i * HH + t];
        int bg = batch[i];
        if (bg != cur) {
            if (cur >= 0) atomicAdd(&g_pool[cur * HH + t], acc);
            cur = bg; acc = 0.f;
        }
        acc += v;
    }
    if (cur >= 0) atomicAdd(&g_pool[cur * HH + t], acc);
    if (t == 0) {
        int c = 0; int cb = -1;
        for (int r = 0; r < 64; r++) {
            int i = base + r;
            if (i >= NN) break;
            int bg = batch[i];
            if (bg != cb) {
                if (cb >= 0) atomicAdd(&g_cnt[cb], (float)c);
                cb = bg; c = 0;
            }
            c++;
        }
        if (cb >= 0) atomicAdd(&g_cnt[cb], (float)c);
    }
}

// ---------------- MLP head + log_softmax ------------------------------------
__global__ void k_head(const float* __restrict__ l1w, const float* __restrict__ l1b,
                       const float* __restrict__ l2w, const float* __restrict__ l2b,
                       float* __restrict__ out) {
    __shared__ float p[HH];
    __shared__ float gg[HH];
    __shared__ float lg[NC];
    const int g = blockIdx.x, t = threadIdx.x;
    float c = fmaxf(g_cnt[g], 1.f);
    p[t] = g_pool[g * HH + t] / c;
    __syncthreads();
    float a = l1b[t];
#pragma unroll 8
    for (int k = 0; k < HH; k++) a += p[k] * l1w[k * HH + t];
    gg[t] = fmaxf(a, 0.f);
    __syncthreads();
    if (t < NC) {
        float a2 = l2b[t];
        for (int k = 0; k < HH; k++) a2 += gg[k] * l2w[k * NC + t];
        lg[t] = a2;
    }
    __syncthreads();
    if (t < NC) {
        float m = lg[0];
        for (int j = 1; j < NC; j++) m = fmaxf(m, lg[j]);
        float s = 0.f;
        for (int j = 0; j < NC; j++) s += expf(lg[j] - m);
        out[g * NC + t] = lg[t] - m - logf(s);
    }
}

// ---------------- launch -----------------------------------------------------
extern "C" void kernel_launch(void* const* d_in, const int* in_sizes, int n_in,
                              void* d_out, int out_size) {
    const float* x     = (const float*)d_in[0];
    const int*   ei    = (const int*)d_in[1];
    const int*   batch = (const int*)d_in[2];
    const float* W1    = (const float*)d_in[3];
    const float* R1    = (const float*)d_in[4];
    const float* b1    = (const float*)d_in[5];
    const float* Wc    = (const float*)d_in[6];
    const float* Rc    = (const float*)d_in[7];
    const float* bc    = (const float*)d_in[8];
    const float* l1w   = (const float*)d_in[9];
    const float* l1b   = (const float*)d_in[10];
    const float* l2w   = (const float*)d_in[11];
    const float* l2b   = (const float*)d_in[12];
    float* out     = (float*)d_out;
    float* lastOut = out + NG * NC;   // tuple order: (log_softmax, last)

    cudaFuncSetAttribute(k_gemm0, cudaFuncAttributeMaxDynamicSharedMemorySize, SM2_TOTAL);
    cudaFuncSetAttribute(k_fused, cudaFuncAttributeMaxDynamicSharedMemorySize, SM2_TOTAL);

    // preprocessing: zero+weight convert fused, then CSR build
    k_pre <<<204, 256>>>(W1, R1, Wc, Rc);
    k_deg <<<(NE + 255) / 256, 256>>>(ei);
    k_off <<<(NN + 255) / 256, 256>>>();
    k_fill<<<(NE + 255) / 256, 256>>>(ei);

    // layer 0: GEMM from fp32 x -> g_h0, g_f
    k_gemm0<<<GEMM_GRID, 256, SM2_TOTAL>>>(x, b1);
    // layers 1-3: fused agg(prev) + GEMM
    k_fused<<<GEMM_GRID, 256, SM2_TOTAL>>>(0, 1, 1, bc + 0 * HH);
    k_fused<<<GEMM_GRID, 256, SM2_TOTAL>>>(1, 0, 2, bc + 1 * HH);
    k_fused<<<GEMM_GRID, 256, SM2_TOTAL>>>(0, 1, 3, bc + 2 * HH);
    // final agg -> fp32 lastOut
    k_aggF<<<(NN + 3) / 4, 128>>>(1, lastOut);

    k_pool<<<(NN + 63) / 64, 128>>>(lastOut, batch);
    k_head<<<NG, 128>>>(l1w, l1b, l2w, l2b, out);
}

// round 15
// speedup vs baseline: 1.4193x; 1.4193x over previous
#include <cuda_runtime.h>
#include <cuda_fp16.h>
#include <cstdint>

#define NN 50000
#define NE 600000
#define HH 128
#define NG 128
#define NC 10
#define NT64 782                    // ceil(50000/64)
#define GEMM_GRID 296               // 2 CTAs per SM, persistent

// ---------------- tile geometry ----------------------------------------------
#define TSTRIDE 272                 // 128 fp16 (256B) + 16B pad -> ldmatrix conflict-free
#define TILE_B  (128 * TSTRIDE)     // 34816 bytes per 128x128 fp16 image

// ---------------- scratch (static device globals; no allocation) ------------
__device__ __half g_h [NN*HH];     // W-path output, fp16
__device__ __half g_f0[NN*HH];     // activation ping (fp16, relu'd by agg)
__device__ __half g_f1[NN*HH];     // activation pong
__device__ uint2 g_edge[NE];       // packed {src, bits(w)} CSR records
__device__ int   g_deg [NN];
__device__ int   g_beg [NN];       // after k_fill: END of each segment
__device__ int   g_total;
__device__ float g_dinv[NN];
__device__ float g_pool[NG*HH];
__device__ float g_cnt [NG];
// fp16 weight images: [layer][W,R][TILE_B] -- W,R contiguous per layer
__device__ __align__(16) char g_wimg[4][2][TILE_B];

__device__ __forceinline__ __half* selBuf(int s) { return s ? g_f1 : g_f0; }

__device__ __forceinline__ uint32_t s2u(const void* p) {
    uint32_t a;
    asm("{ .reg .u64 t; cvta.to.shared.u64 t, %1; cvt.u32.u64 %0, t; }"
        : "=r"(a) : "l"(p));
    return a;
}

// ---------------- GEMM SMEM layout (per CTA: 87040 B -> 2 CTA/SM) -----------
#define A16  0
#define BW16 17408                  // W image
#define BR16 (17408 + TILE_B)       // R image
#define SM2_TOTAL (17408 + 2 * TILE_B)   // 87040

__device__ __forceinline__ void ldm4(uint32_t* r, uint32_t addr) {
    asm volatile("ldmatrix.sync.aligned.m8n8.x4.shared.b16 {%0,%1,%2,%3}, [%4];"
                 : "=r"(r[0]), "=r"(r[1]), "=r"(r[2]), "=r"(r[3]) : "r"(addr));
}
__device__ __forceinline__ void mma16816h(float* c, const uint32_t* a,
                                          uint32_t b0, uint32_t b1) {
    asm volatile(
        "mma.sync.aligned.m16n8k16.row.col.f32.f16.f16.f32 "
        "{%0,%1,%2,%3}, {%4,%5,%6,%7}, {%8,%9}, {%0,%1,%2,%3};"
        : "+f"(c[0]), "+f"(c[1]), "+f"(c[2]), "+f"(c[3])
        : "r"(a[0]), "r"(a[1]), "r"(a[2]), "r"(a[3]), "r"(b0), "r"(b1));
}

__device__ __forceinline__ uint32_t packh2(float a, float b) {
    __half2 h = __floats2half2_rn(a, b);
    return *(uint32_t*)&h;
}

// ---------------- fused: zero scratch + fp16 weight images ------------------
__global__ void k_pre(const float* __restrict__ W1, const float* __restrict__ R1,
                      const float* __restrict__ Wc, const float* __restrict__ Rc) {
    if (blockIdx.x < 196) {
        int i = blockIdx.x * 256 + threadIdx.x;
        if (i < NN) g_deg[i] = 0;
        if (i < NG*HH) g_pool[i] = 0.f;
        if (i < NG) g_cnt[i] = 0.f;
        if (i == 0) g_total = 0;
        return;
    }
    const int b = blockIdx.x - 196;
    const int layer = b >> 1;
    const int isR = b & 1;
    const float* src;
    if (layer == 0) src = isR ? R1 : W1;
    else src = (isR ? Rc : Wc) + (layer - 1) * HH * HH;
    char* img = g_wimg[layer][isR];
    for (int idx = threadIdx.x; idx < HH * HH; idx += 256) {
        int n = idx >> 7, k = idx & 127;
        __half h = __float2half(src[k * HH + n]);   // transpose [k][n] -> [n][k]
        *(unsigned short*)(img + n * TSTRIDE + k * 2) = *(unsigned short*)&h;
    }
}

// ---------------- persistent fused dual-output GEMM --------------------------
// one CTA per tile computes BOTH: g_h = X@W (fp16) and f16 = X@R + bias (fp16)
// X: layer 0 = external fp32 x (no relu); layers 1-3 = fp16 buffer (already relu'd)
__global__ void __launch_bounds__(256, 2) k_mmagemm(
    const float* __restrict__ Xext, int inSel, int outSel, int layer,
    const float* __restrict__ bias)
{
    extern __shared__ char smem[];
    const uint32_t sbase = s2u(smem);
    const int tid = threadIdx.x;
    const int wid = tid >> 5, lane = tid & 31;
    const __half* X16 = (inSel < 0) ? (const __half*)0 : selBuf(inSel);
    __half* dstF = selBuf(outSel);

    // ---- both B images (69632 B contiguous) loaded ONCE per CTA ----
    {
        const float4* src = (const float4*)g_wimg[layer][0];
        float4* d4 = (float4*)(smem + BW16);
#pragma unroll
        for (int it = 0; it < 17; it++)
            d4[it * 256 + tid] = src[it * 256 + tid];
    }

    // warp decomposition
    const int wm = wid & 1;
    const int wn = wid >> 1;           // 0..3
    const int n0 = wn * 32;
    const uint32_t aOff = (uint32_t)((wm * 32 + (lane & 15)) * TSTRIDE
                                     + (lane >> 4) * 16);
    const int q = lane >> 3, r8 = lane & 7;
    const uint32_t bOff = (uint32_t)((n0 + ((q & 2) << 2) + r8) * TSTRIDE
                                     + (q & 1) * 16);
    const uint32_t aB = sbase + A16;
    const uint32_t bWB = sbase + BW16, bRB = sbase + BR16;
    const int gq = lane >> 2, t4 = lane & 3;

    float bx[4], by[4];
#pragma unroll
    for (int nf = 0; nf < 4; nf++) {
        float2 bv = *(const float2*)(bias + n0 + nf * 8 + 2 * t4);
        bx[nf] = bv.x; by[nf] = bv.y;
    }

    const int lm = tid >> 5;           // fp32 A-load base row
    const int lc4 = (tid & 31) * 4;    // fp32 A-load col
    const int hm = tid >> 4;           // fp16 A-load: rows hm + it*16
    const int hc8 = (tid & 15) * 8;    // fp16 A-load col (8 halves = 16B)

    for (int tile = blockIdx.x; tile < NT64; tile += GEMM_GRID) {
        const int row0 = tile * 64;

        __syncthreads();   // previous mainloop done reading A
        if (inSel < 0) {
            // ---- layer 0: 64x128 fp32 -> fp16 ----
#pragma unroll
            for (int it = 0; it < 8; it++) {
                int gr = row0 + lm + it * 8;
                float4 w = (gr < NN) ? *(const float4*)(Xext + gr * 128 + lc4)
                                     : make_float4(0.f, 0.f, 0.f, 0.f);
                uint32_t bo = (lm + it * 8) * TSTRIDE + lc4 * 2;
                *(uint32_t*)(smem + A16 + bo)     = packh2(w.x, w.y);
                *(uint32_t*)(smem + A16 + bo + 4) = packh2(w.z, w.w);
            }
        } else {
            // ---- layers 1-3: straight fp16 16B copies ----
#pragma unroll
            for (int it = 0; it < 4; it++) {
                int m = hm + it * 16;
                int gr = row0 + m;
                uint4 w = (gr < NN) ? *(const uint4*)(X16 + gr * 128 + hc8)
                                    : make_uint4(0u, 0u, 0u, 0u);
                *(uint4*)(smem + A16 + m * TSTRIDE + hc8 * 2) = w;
            }
        }
        __syncthreads();

        float cW[2][4][4], cR[2][4][4];
#pragma unroll
        for (int i = 0; i < 2; i++)
#pragma unroll
            for (int j = 0; j < 4; j++)
#pragma unroll
                for (int z = 0; z < 4; z++) { cW[i][j][z] = 0.f; cR[i][j][z] = 0.f; }

#pragma unroll 1
        for (int k0 = 0; k0 < 128; k0 += 16) {
            const uint32_t kB = (uint32_t)(k0 * 2);
            uint32_t a[2][4];
#pragma unroll
            for (int mf = 0; mf < 2; mf++)
                ldm4(a[mf], aB + aOff + mf * (16 * TSTRIDE) + kB);
#pragma unroll
            for (int nf2 = 0; nf2 < 2; nf2++) {
                uint32_t bb[4];
                ldm4(bb, bWB + bOff + nf2 * (16 * TSTRIDE) + kB);
#pragma unroll
                for (int mf = 0; mf < 2; mf++) {
                    mma16816h(cW[mf][nf2 * 2],     a[mf], bb[0], bb[1]);
                    mma16816h(cW[mf][nf2 * 2 + 1], a[mf], bb[2], bb[3]);
                }
                ldm4(bb, bRB + bOff + nf2 * (16 * TSTRIDE) + kB);
#pragma unroll
                for (int mf = 0; mf < 2; mf++) {
                    mma16816h(cR[mf][nf2 * 2],     a[mf], bb[0], bb[1]);
                    mma16816h(cR[mf][nf2 * 2 + 1], a[mf], bb[2], bb[3]);
                }
            }
        }

        // ---- epilogue: W -> fp16 g_h ; R + bias -> fp16 f ----
#pragma unroll
        for (int nf = 0; nf < 4; nf++) {
            const int col = n0 + nf * 8 + 2 * t4;
#pragma unroll
            for (int mf = 0; mf < 2; mf++) {
                int rlo = row0 + wm * 32 + mf * 16 + gq;
                if (rlo < NN) {
                    *(__half2*)(g_h + rlo * 128 + col) =
                        __floats2half2_rn(cW[mf][nf][0], cW[mf][nf][1]);
                    *(__half2*)(dstF + rlo * 128 + col) =
                        __floats2half2_rn(cR[mf][nf][0] + bx[nf], cR[mf][nf][1] + by[nf]);
                }
                if (rlo + 8 < NN) {
                    *(__half2*)(g_h + (rlo + 8) * 128 + col) =
                        __floats2half2_rn(cW[mf][nf][2], cW[mf][nf][3]);
                    *(__half2*)(dstF + (rlo + 8) * 128 + col) =
                        __floats2half2_rn(cR[mf][nf][2] + bx[nf], cR[mf][nf][3] + by[nf]);
                }
            }
        }
    }
}

// ---------------- graph preprocessing --------------------------------------
__global__ void k_deg(const int* __restrict__ ei) {
    int e = blockIdx.x * blockDim.x + threadIdx.x;
    if (e < NE) {
        int d = ei[NE + e];
        if (d >= 0 && d < NN) atomicAdd(&g_deg[d], 1);
    }
}

__global__ void k_off() {
    __shared__ int sh[256];
    __shared__ int base;
    const int t = threadIdx.x;
    const int i = blockIdx.x * 256 + t;
    int d = (i < NN) ? g_deg[i] : 0;
    if (i < NN) g_dinv[i] = (d > 0) ? rsqrtf((float)d) : 0.f;
    sh[t] = d;
    __syncthreads();
    for (int off = 1; off < 256; off <<= 1) {
        int v = (t >= off) ? sh[t - off] : 0;
        __syncthreads();
        sh[t] += v;
        __syncthreads();
    }
    if (t == 255) base = atomicAdd(&g_total, sh[255]);
    __syncthreads();
    if (i < NN) g_beg[i] = base + sh[t] - d;
}

// fill atomics run directly on g_beg; afterwards g_beg[i] == segment END
__global__ void k_fill(const int* __restrict__ ei) {
    int e = blockIdx.x * blockDim.x + threadIdx.x;
    if (e < NE) {
        int s = ei[e];
        int d = ei[NE + e];
        if (s < 0 || s >= NN || d < 0 || d >= NN) return;
        float w = g_dinv[s] * g_dinv[d];
        int pos = atomicAdd(&g_beg[d], 1);
        g_edge[pos] = make_uint2((uint32_t)s, __float_as_uint(w));
    }
}

// ---------------- CSR aggregation: warp per node, half-warp per edge --------
// lanes 0-15 process even edges, lanes 16-31 odd edges; each lane covers
// 8 fp16 features (16B). Partial sums combined via shfl_xor(16).
// relu applied here; non-last: write fp16 next-layer input; last: fp32 lastOut
__global__ void k_agg(int outSel, int last, float* __restrict__ lastOut) {
    __half* f = selBuf(outSel);
    const int wid = threadIdx.x >> 5, lane = threadIdx.x & 31;
    const int i = blockIdx.x * 4 + wid;
    if (i >= NN) return;
    const int end = g_beg[i];
    const int beg = end - g_deg[i];
    const int half = lane >> 4;
    const int hoff = (lane & 15) * 8;      // feature offset in halves (16B)

    float acc[8];
    if (half == 0) {
        // init: skip connection (counted once, by half 0)
        uint4 u = *(const uint4*)(f + i * HH + hoff);
        float2 p0 = __half22float2(*(__half2*)&u.x);
        float2 p1 = __half22float2(*(__half2*)&u.y);
        float2 p2 = __half22float2(*(__half2*)&u.z);
        float2 p3 = __half22float2(*(__half2*)&u.w);
        acc[0] = p0.x; acc[1] = p0.y; acc[2] = p1.x; acc[3] = p1.y;
        acc[4] = p2.x; acc[5] = p2.y; acc[6] = p3.x; acc[7] = p3.y;
    } else {
#pragma unroll
        for (int k = 0; k < 8; k++) acc[k] = 0.f;
    }

    int e = beg + half;
    // unrolled: this half consumes edges e, e+2 per iteration
    for (; e + 2 < end; e += 4) {
        uint2 ed0 = g_edge[e];
        uint2 ed1 = g_edge[e + 2];
        float w0 = __uint_as_float(ed0.y);
        float w1 = __uint_as_float(ed1.y);
        uint4 u0 = *(const uint4*)(g_h + ed0.x * HH + hoff);
        uint4 u1 = *(const uint4*)(g_h + ed1.x * HH + hoff);
        float2 a0 = __half22float2(*(__half2*)&u0.x), a1 = __half22float2(*(__half2*)&u0.y);
        float2 a2 = __half22float2(*(__half2*)&u0.z), a3 = __half22float2(*(__half2*)&u0.w);
        float2 b0 = __half22float2(*(__half2*)&u1.x), b1 = __half22float2(*(__half2*)&u1.y);
        float2 b2 = __half22float2(*(__half2*)&u1.z), b3 = __half22float2(*(__half2*)&u1.w);
        acc[0] += a0.x * w0 + b0.x * w1;
        acc[1] += a0.y * w0 + b0.y * w1;
        acc[2] += a1.x * w0 + b1.x * w1;
        acc[3] += a1.y * w0 + b1.y * w1;
        acc[4] += a2.x * w0 + b2.x * w1;
        acc[5] += a2.y * w0 + b2.y * w1;
        acc[6] += a3.x * w0 + b3.x * w1;
        acc[7] += a3.y * w0 + b3.y * w1;
    }
    if (e < end) {
        uint2 ed = g_edge[e];
        float w = __uint_as_float(ed.y);
        uint4 u = *(const uint4*)(g_h + ed.x * HH + hoff);
        float2 a0 = __half22float2(*(__half2*)&u.x), a1 = __half22float2(*(__half2*)&u.y);
        float2 a2 = __half22float2(*(__half2*)&u.z), a3 = __half22float2(*(__half2*)&u.w);
        acc[0] += a0.x * w; acc[1] += a0.y * w;
        acc[2] += a1.x * w; acc[3] += a1.y * w;
        acc[4] += a2.x * w; acc[5] += a2.y * w;
        acc[6] += a3.x * w; acc[7] += a3.y * w;
    }

    // combine halves + relu
#pragma unroll
    for (int k = 0; k < 8; k++) {
        acc[k] += __shfl_xor_sync(0xFFFFFFFFu, acc[k], 16);
        acc[k] = fmaxf(acc[k], 0.f);
    }

    if (half == 0) {
        if (last) {
            float4 o0 = make_float4(acc[0], acc[1], acc[2], acc[3]);
            float4 o1 = make_float4(acc[4], acc[5], acc[6], acc[7]);
            *(float4*)(lastOut + i * HH + hoff)     = o0;
            *(float4*)(lastOut + i * HH + hoff + 4) = o1;
        } else {
            uint4 o;
            *(__half2*)&o.x = __floats2half2_rn(acc[0], acc[1]);
            *(__half2*)&o.y = __floats2half2_rn(acc[2], acc[3]);
            *(__half2*)&o.z = __floats2half2_rn(acc[4], acc[5]);
            *(__half2*)&o.w = __floats2half2_rn(acc[6], acc[7]);
            *(uint4*)(f + i * HH + hoff) = o;
        }
    }
}

// ---------------- mean-pool accumulation (input already relu'd) -------------
__global__ void k_pool(const float* __restrict__ f,
                       const int* __restrict__ batch) {
    const int t = threadIdx.x;
    const int base = blockIdx.x * 64;
    float acc = 0.f;
    int cur = -1;
    for (int r = 0; r < 64; r++) {
        int i = base + r;
        if (i >= NN) break;
        float v = f[i * HH + t];
        int bg = batch[i];
        if (bg != cur) {
            if (cur >= 0) atomicAdd(&g_pool[cur * HH + t], acc);
            cur = bg; acc = 0.f;
        }
        acc += v;
    }
    if (cur >= 0) atomicAdd(&g_pool[cur * HH + t], acc);
    if (t == 0) {
        int c = 0; int cb = -1;
        for (int r = 0; r < 64; r++) {
            int i = base + r;
            if (i >= NN) break;
            int bg = batch[i];
            if (bg != cb) {
                if (cb >= 0) atomicAdd(&g_cnt[cb], (float)c);
                cb = bg; c = 0;
            }
            c++;
        }
        if (cb >= 0) atomicAdd(&g_cnt[cb], (float)c);
    }
}

// ---------------- MLP head + log_softmax ------------------------------------
__global__ void k_head(const float* __restrict__ l1w, const float* __restrict__ l1b,
                       const float* __restrict__ l2w, const float* __restrict__ l2b,
                       float* __restrict__ out) {
    __shared__ float p[HH];
    __shared__ float gg[HH];
    __shared__ float lg[NC];
    const int g = blockIdx.x, t = threadIdx.x;
    float c = fmaxf(g_cnt[g], 1.f);
    p[t] = g_pool[g * HH + t] / c;
    __syncthreads();
    float a = l1b[t];
#pragma unroll 8
    for (int k = 0; k < HH; k++) a += p[k] * l1w[k * HH + t];
    gg[t] = fmaxf(a, 0.f);
    __syncthreads();
    if (t < NC) {
        float a2 = l2b[t];
        for (int k = 0; k < HH; k++) a2 += gg[k] * l2w[k * NC + t];
        lg[t] = a2;
    }
    __syncthreads();
    if (t < NC) {
        float m = lg[0];
        for (int j = 1; j < NC; j++) m = fmaxf(m, lg[j]);
        float s = 0.f;
        for (int j = 0; j < NC; j++) s += expf(lg[j] - m);
        out[g * NC + t] = lg[t] - m - logf(s);
    }
}

// ---------------- launch -----------------------------------------------------
extern "C" void kernel_launch(void* const* d_in, const int* in_sizes, int n_in,
                              void* d_out, int out_size) {
    const float* x     = (const float*)d_in[0];
    const int*   ei    = (const int*)d_in[1];
    const int*   batch = (const int*)d_in[2];
    const float* W1    = (const float*)d_in[3];
    const float* R1    = (const float*)d_in[4];
    const float* b1    = (const float*)d_in[5];
    const float* Wc    = (const float*)d_in[6];
    const float* Rc    = (const float*)d_in[7];
    const float* bc    = (const float*)d_in[8];
    const float* l1w   = (const float*)d_in[9];
    const float* l1b   = (const float*)d_in[10];
    const float* l2w   = (const float*)d_in[11];
    const float* l2b   = (const float*)d_in[12];
    float* out     = (float*)d_out;
    float* lastOut = out + NG * NC;   // tuple order: (log_softmax, last)

    cudaFuncSetAttribute(k_mmagemm, cudaFuncAttributeMaxDynamicSharedMemorySize, SM2_TOTAL);

    // preprocessing: zero+weight convert fused, then CSR build
    k_pre <<<204, 256>>>(W1, R1, Wc, Rc);
    k_deg <<<(NE + 255) / 256, 256>>>(ei);
    k_off <<<(NN + 255) / 256, 256>>>();
    k_fill<<<(NE + 255) / 256, 256>>>(ei);

    // 4 GCS layers; relu lives in k_agg; last agg writes fp32 lastOut
    int inSel = -1;
    int outSel = 0;
    for (int l = 0; l < 4; l++) {
        const float* b = (l == 0) ? b1 : bc + (l - 1) * HH;
        k_mmagemm<<<GEMM_GRID, 256, SM2_TOTAL>>>(x, inSel, outSel, l, b);
        k_agg<<<(NN + 3) / 4, 128>>>(outSel, (l == 3) ? 1 : 0, lastOut);
        inSel = outSel;
        outSel ^= 1;
    }

    k_pool<<<(NN + 63) / 64, 128>>>(lastOut, batch);
    k_head<<<NG, 128>>>(l1w, l1b, l2w, l2b, out);
}

// round 16
// speedup vs baseline: 1.4968x; 1.0546x over previous
#include <cuda_runtime.h>
#include <cuda_fp16.h>
#include <cstdint>

#define NN 50000
#define NE 600000
#define HH 128
#define NG 128
#define NC 10
#define NT64 782                    // ceil(50000/64)
#define GEMM_GRID 296               // 2 CTAs per SM, persistent

// ---------------- tile geometry ----------------------------------------------
#define TSTRIDE 272                 // 128 fp16 (256B) + 16B pad -> ldmatrix conflict-free
#define TILE_B  (128 * TSTRIDE)     // 34816 bytes per 128x128 fp16 image

// ---------------- scratch (static device globals; no allocation) ------------
__device__ __half g_h [NN*HH];     // W-path output, fp16
__device__ __half g_f0[NN*HH];     // activation ping (fp16, relu'd by agg)
__device__ __half g_f1[NN*HH];     // activation pong
__device__ uint2 g_edge[NE];       // packed {src, bits(w)} CSR records
__device__ int   g_deg [NN];
__device__ int   g_beg [NN];       // after k_fill: END of each segment
__device__ int   g_total;
__device__ float g_dinv[NN];
__device__ float g_pool[NG*HH];
__device__ float g_cnt [NG];
// fp16 weight images: [layer][W,R][TILE_B] -- W,R contiguous per layer
__device__ __align__(16) char g_wimg[4][2][TILE_B];

__device__ __forceinline__ __half* selBuf(int s) { return s ? g_f1 : g_f0; }

__device__ __forceinline__ uint32_t s2u(const void* p) {
    uint32_t a;
    asm("{ .reg .u64 t; cvta.to.shared.u64 t, %1; cvt.u32.u64 %0, t; }"
        : "=r"(a) : "l"(p));
    return a;
}

// ---------------- GEMM SMEM layout (per CTA: 87040 B -> 2 CTA/SM) -----------
#define A16  0
#define BW16 17408                  // W image
#define BR16 (17408 + TILE_B)       // R image
#define SM2_TOTAL (17408 + 2 * TILE_B)   // 87040

__device__ __forceinline__ void ldm4(uint32_t* r, uint32_t addr) {
    asm volatile("ldmatrix.sync.aligned.m8n8.x4.shared.b16 {%0,%1,%2,%3}, [%4];"
                 : "=r"(r[0]), "=r"(r[1]), "=r"(r[2]), "=r"(r[3]) : "r"(addr));
}
__device__ __forceinline__ void mma16816h(float* c, const uint32_t* a,
                                          uint32_t b0, uint32_t b1) {
    asm volatile(
        "mma.sync.aligned.m16n8k16.row.col.f32.f16.f16.f32 "
        "{%0,%1,%2,%3}, {%4,%5,%6,%7}, {%8,%9}, {%0,%1,%2,%3};"
        : "+f"(c[0]), "+f"(c[1]), "+f"(c[2]), "+f"(c[3])
        : "r"(a[0]), "r"(a[1]), "r"(a[2]), "r"(a[3]), "r"(b0), "r"(b1));
}

__device__ __forceinline__ uint32_t packh2(float a, float b) {
    __half2 h = __floats2half2_rn(a, b);
    return *(uint32_t*)&h;
}

// ---------------- zero scratch ------------------------------------------------
__global__ void k_pre() {
    int i = blockIdx.x * 256 + threadIdx.x;
    if (i < NN) g_deg[i] = 0;
    if (i < NG*HH) g_pool[i] = 0.f;
    if (i < NG) g_cnt[i] = 0.f;
    if (i == 0) g_total = 0;
}

// ---------------- degree histogram + (concurrent) fp16 weight images --------
// blocks [0, 2344): degree atomics; blocks [2344, 2352): weight split
__global__ void k_deg(const int* __restrict__ ei,
                      const float* __restrict__ W1, const float* __restrict__ R1,
                      const float* __restrict__ Wc, const float* __restrict__ Rc) {
    if (blockIdx.x < 2344) {
        int e = blockIdx.x * 256 + threadIdx.x;
        if (e < NE) {
            int d = ei[NE + e];
            if (d >= 0 && d < NN) atomicAdd(&g_deg[d], 1);
        }
        return;
    }
    const int b = blockIdx.x - 2344;
    const int layer = b >> 1;
    const int isR = b & 1;
    const float* src;
    if (layer == 0) src = isR ? R1 : W1;
    else src = (isR ? Rc : Wc) + (layer - 1) * HH * HH;
    char* img = g_wimg[layer][isR];
    for (int idx = threadIdx.x; idx < HH * HH; idx += 256) {
        int n = idx >> 7, k = idx & 127;
        __half h = __float2half(src[k * HH + n]);   // transpose [k][n] -> [n][k]
        *(unsigned short*)(img + n * TSTRIDE + k * 2) = *(unsigned short*)&h;
    }
}

// ---------------- persistent fused dual-output GEMM --------------------------
// one CTA per tile computes BOTH: g_h = X@W (fp16) and f16 = X@R + bias (fp16)
// X: layer 0 = external fp32 x (no relu); layers 1-3 = fp16 buffer (already relu'd)
__global__ void __launch_bounds__(256, 2) k_mmagemm(
    const float* __restrict__ Xext, int inSel, int outSel, int layer,
    const float* __restrict__ bias)
{
    extern __shared__ char smem[];
    const uint32_t sbase = s2u(smem);
    const int tid = threadIdx.x;
    const int wid = tid >> 5, lane = tid & 31;
    const __half* X16 = (inSel < 0) ? (const __half*)0 : selBuf(inSel);
    __half* dstF = selBuf(outSel);

    // ---- both B images (69632 B contiguous) loaded ONCE per CTA ----
    {
        const float4* src = (const float4*)g_wimg[layer][0];
        float4* d4 = (float4*)(smem + BW16);
#pragma unroll
        for (int it = 0; it < 17; it++)
            d4[it * 256 + tid] = src[it * 256 + tid];
    }

    // warp decomposition
    const int wm = wid & 1;
    const int wn = wid >> 1;           // 0..3
    const int n0 = wn * 32;
    const uint32_t aOff = (uint32_t)((wm * 32 + (lane & 15)) * TSTRIDE
                                     + (lane >> 4) * 16);
    const int q = lane >> 3, r8 = lane & 7;
    const uint32_t bOff = (uint32_t)((n0 + ((q & 2) << 2) + r8) * TSTRIDE
                                     + (q & 1) * 16);
    const uint32_t aB = sbase + A16;
    const uint32_t bWB = sbase + BW16, bRB = sbase + BR16;
    const int gq = lane >> 2, t4 = lane & 3;

    float bx[4], by[4];
#pragma unroll
    for (int nf = 0; nf < 4; nf++) {
        float2 bv = *(const float2*)(bias + n0 + nf * 8 + 2 * t4);
        bx[nf] = bv.x; by[nf] = bv.y;
    }

    const int lm = tid >> 5;           // fp32 A-load base row
    const int lc4 = (tid & 31) * 4;    // fp32 A-load col
    const int hm = tid >> 4;           // fp16 A-load: rows hm + it*16
    const int hc8 = (tid & 15) * 8;    // fp16 A-load col (8 halves = 16B)

    for (int tile = blockIdx.x; tile < NT64; tile += GEMM_GRID) {
        const int row0 = tile * 64;

        __syncthreads();   // previous mainloop done reading A
        if (inSel < 0) {
            // ---- layer 0: 64x128 fp32 -> fp16 ----
#pragma unroll
            for (int it = 0; it < 8; it++) {
                int gr = row0 + lm + it * 8;
                float4 w = (gr < NN) ? *(const float4*)(Xext + gr * 128 + lc4)
                                     : make_float4(0.f, 0.f, 0.f, 0.f);
                uint32_t bo = (lm + it * 8) * TSTRIDE + lc4 * 2;
                *(uint32_t*)(smem + A16 + bo)     = packh2(w.x, w.y);
                *(uint32_t*)(smem + A16 + bo + 4) = packh2(w.z, w.w);
            }
        } else {
            // ---- layers 1-3: straight fp16 16B copies ----
#pragma unroll
            for (int it = 0; it < 4; it++) {
                int m = hm + it * 16;
                int gr = row0 + m;
                uint4 w = (gr < NN) ? *(const uint4*)(X16 + gr * 128 + hc8)
                                    : make_uint4(0u, 0u, 0u, 0u);
                *(uint4*)(smem + A16 + m * TSTRIDE + hc8 * 2) = w;
            }
        }
        __syncthreads();

        float cW[2][4][4], cR[2][4][4];
#pragma unroll
        for (int i = 0; i < 2; i++)
#pragma unroll
            for (int j = 0; j < 4; j++)
#pragma unroll
                for (int z = 0; z < 4; z++) { cW[i][j][z] = 0.f; cR[i][j][z] = 0.f; }

#pragma unroll 1
        for (int k0 = 0; k0 < 128; k0 += 16) {
            const uint32_t kB = (uint32_t)(k0 * 2);
            uint32_t a[2][4];
#pragma unroll
            for (int mf = 0; mf < 2; mf++)
                ldm4(a[mf], aB + aOff + mf * (16 * TSTRIDE) + kB);
#pragma unroll
            for (int nf2 = 0; nf2 < 2; nf2++) {
                uint32_t bb[4];
                ldm4(bb, bWB + bOff + nf2 * (16 * TSTRIDE) + kB);
#pragma unroll
                for (int mf = 0; mf < 2; mf++) {
                    mma16816h(cW[mf][nf2 * 2],     a[mf], bb[0], bb[1]);
                    mma16816h(cW[mf][nf2 * 2 + 1], a[mf], bb[2], bb[3]);
                }
                ldm4(bb, bRB + bOff + nf2 * (16 * TSTRIDE) + kB);
#pragma unroll
                for (int mf = 0; mf < 2; mf++) {
                    mma16816h(cR[mf][nf2 * 2],     a[mf], bb[0], bb[1]);
                    mma16816h(cR[mf][nf2 * 2 + 1], a[mf], bb[2], bb[3]);
                }
            }
        }

        // ---- epilogue: W -> fp16 g_h ; R + bias -> fp16 f ----
#pragma unroll
        for (int nf = 0; nf < 4; nf++) {
            const int col = n0 + nf * 8 + 2 * t4;
#pragma unroll
            for (int mf = 0; mf < 2; mf++) {
                int rlo = row0 + wm * 32 + mf * 16 + gq;
                if (rlo < NN) {
                    *(__half2*)(g_h + rlo * 128 + col) =
                        __floats2half2_rn(cW[mf][nf][0], cW[mf][nf][1]);
                    *(__half2*)(dstF + rlo * 128 + col) =
                        __floats2half2_rn(cR[mf][nf][0] + bx[nf], cR[mf][nf][1] + by[nf]);
                }
                if (rlo + 8 < NN) {
                    *(__half2*)(g_h + (rlo + 8) * 128 + col) =
                        __floats2half2_rn(cW[mf][nf][2], cW[mf][nf][3]);
                    *(__half2*)(dstF + (rlo + 8) * 128 + col) =
                        __floats2half2_rn(cR[mf][nf][2] + bx[nf], cR[mf][nf][3] + by[nf]);
                }
            }
        }
    }
}

// ---------------- CSR offsets (fused dinv + scan) ----------------------------
__global__ void k_off() {
    __shared__ int sh[256];
    __shared__ int base;
    const int t = threadIdx.x;
    const int i = blockIdx.x * 256 + t;
    int d = (i < NN) ? g_deg[i] : 0;
    if (i < NN) g_dinv[i] = (d > 0) ? rsqrtf((float)d) : 0.f;
    sh[t] = d;
    __syncthreads();
    for (int off = 1; off < 256; off <<= 1) {
        int v = (t >= off) ? sh[t - off] : 0;
        __syncthreads();
        sh[t] += v;
        __syncthreads();
    }
    if (t == 255) base = atomicAdd(&g_total, sh[255]);
    __syncthreads();
    if (i < NN) g_beg[i] = base + sh[t] - d;
}

// fill atomics run directly on g_beg; afterwards g_beg[i] == segment END
__global__ void k_fill(const int* __restrict__ ei) {
    int e = blockIdx.x * blockDim.x + threadIdx.x;
    if (e < NE) {
        int s = ei[e];
        int d = ei[NE + e];
        if (s < 0 || s >= NN || d < 0 || d >= NN) return;
        float w = g_dinv[s] * g_dinv[d];
        int pos = atomicAdd(&g_beg[d], 1);
        g_edge[pos] = make_uint2((uint32_t)s, __float_as_uint(w));
    }
}

// ---------------- CSR aggregation: warp per node, fp16 gather ---------------
// relu applied here; non-last: write fp16 next-layer input; last: fp32 lastOut
__global__ void k_agg(int outSel, int last, float* __restrict__ lastOut) {
    __half* f = selBuf(outSel);
    const int wid = threadIdx.x >> 5, lane = threadIdx.x & 31;
    const int i = blockIdx.x * 4 + wid;
    if (i >= NN) return;
    const int end = g_beg[i];
    const int beg = end - g_deg[i];
    const int laneOff = lane * 4;
    // init: skip connection (fp16 f from GEMM) -> fp32
    float4 acc;
    {
        uint2 u = *(const uint2*)(f + i * HH + laneOff);
        float2 a = __half22float2(*(__half2*)&u.x), b = __half22float2(*(__half2*)&u.y);
        acc = make_float4(a.x, a.y, b.x, b.y);
    }
    int e = beg;
    for (; e + 4 <= end; e += 4) {
        uint2 e0 = g_edge[e],   e1 = g_edge[e+1];
        uint2 e2 = g_edge[e+2], e3 = g_edge[e+3];
        float w0 = __uint_as_float(e0.y), w1 = __uint_as_float(e1.y);
        float w2 = __uint_as_float(e2.y), w3 = __uint_as_float(e3.y);
        uint2 u0 = *(const uint2*)(g_h + e0.x * HH + laneOff);
        uint2 u1 = *(const uint2*)(g_h + e1.x * HH + laneOff);
        uint2 u2 = *(const uint2*)(g_h + e2.x * HH + laneOff);
        uint2 u3 = *(const uint2*)(g_h + e3.x * HH + laneOff);
        float2 a0 = __half22float2(*(__half2*)&u0.x), b0 = __half22float2(*(__half2*)&u0.y);
        float2 a1 = __half22float2(*(__half2*)&u1.x), b1 = __half22float2(*(__half2*)&u1.y);
        float2 a2 = __half22float2(*(__half2*)&u2.x), b2 = __half22float2(*(__half2*)&u2.y);
        float2 a3 = __half22float2(*(__half2*)&u3.x), b3 = __half22float2(*(__half2*)&u3.y);
        acc.x += a0.x*w0 + a1.x*w1 + a2.x*w2 + a3.x*w3;
        acc.y += a0.y*w0 + a1.y*w1 + a2.y*w2 + a3.y*w3;
        acc.z += b0.x*w0 + b1.x*w1 + b2.x*w2 + b3.x*w3;
        acc.w += b0.y*w0 + b1.y*w1 + b2.y*w2 + b3.y*w3;
    }
    for (; e < end; e++) {
        uint2 ed = g_edge[e];
        float w = __uint_as_float(ed.y);
        uint2 u = *(const uint2*)(g_h + ed.x * HH + laneOff);
        float2 a = __half22float2(*(__half2*)&u.x), b = __half22float2(*(__half2*)&u.y);
        acc.x += a.x * w; acc.y += a.y * w;
        acc.z += b.x * w; acc.w += b.y * w;
    }
    acc.x = fmaxf(acc.x, 0.f); acc.y = fmaxf(acc.y, 0.f);
    acc.z = fmaxf(acc.z, 0.f); acc.w = fmaxf(acc.w, 0.f);
    if (last) {
        *(float4*)(lastOut + i * HH + laneOff) = acc;
    } else {
        uint2 o;
        *(__half2*)&o.x = __floats2half2_rn(acc.x, acc.y);
        *(__half2*)&o.y = __floats2half2_rn(acc.z, acc.w);
        *(uint2*)(f + i * HH + laneOff) = o;
    }
}

// ---------------- mean-pool accumulation (input already relu'd) -------------
__global__ void k_pool(const float* __restrict__ f,
                       const int* __restrict__ batch) {
    const int t = threadIdx.x;
    const int base = blockIdx.x * 64;
    float acc = 0.f;
    int cur = -1;
    for (int r = 0; r < 64; r++) {
        int i = base + r;
        if (i >= NN) break;
        float v = f[i * HH + t];
        int bg = batch[i];
        if (bg != cur) {
            if (cur >= 0) atomicAdd(&g_pool[cur * HH + t], acc);
            cur = bg; acc = 0.f;
        }
        acc += v;
    }
    if (cur >= 0) atomicAdd(&g_pool[cur * HH + t], acc);
    if (t == 0) {
        int c = 0; int cb = -1;
        for (int r = 0; r < 64; r++) {
            int i = base + r;
            if (i >= NN) break;
            int bg = batch[i];
            if (bg != cb) {
                if (cb >= 0) atomicAdd(&g_cnt[cb], (float)c);
                cb = bg; c = 0;
            }
            c++;
        }
        if (cb >= 0) atomicAdd(&g_cnt[cb], (float)c);
    }
}

// ---------------- MLP head + log_softmax ------------------------------------
__global__ void k_head(const float* __restrict__ l1w, const float* __restrict__ l1b,
                       const float* __restrict__ l2w, const float* __restrict__ l2b,
                       float* __restrict__ out) {
    __shared__ float p[HH];
    __shared__ float gg[HH];
    __shared__ float lg[NC];
    const int g = blockIdx.x, t = threadIdx.x;
    float c = fmaxf(g_cnt[g], 1.f);
    p[t] = g_pool[g * HH + t] / c;
    __syncthreads();
    float a = l1b[t];
#pragma unroll 8
    for (int k = 0; k < HH; k++) a += p[k] * l1w[k * HH + t];
    gg[t] = fmaxf(a, 0.f);
    __syncthreads();
    if (t < NC) {
        float a2 = l2b[t];
        for (int k = 0; k < HH; k++) a2 += gg[k] * l2w[k * NC + t];
        lg[t] = a2;
    }
    __syncthreads();
    if (t < NC) {
        float m = lg[0];
        for (int j = 1; j < NC; j++) m = fmaxf(m, lg[j]);
        float s = 0.f;
        for (int j = 0; j < NC; j++) s += expf(lg[j] - m);
        out[g * NC + t] = lg[t] - m - logf(s);
    }
}

// ---------------- launch -----------------------------------------------------
extern "C" void kernel_launch(void* const* d_in, const int* in_sizes, int n_in,
                              void* d_out, int out_size) {
    const float* x     = (const float*)d_in[0];
    const int*   ei    = (const int*)d_in[1];
    const int*   batch = (const int*)d_in[2];
    const float* W1    = (const float*)d_in[3];
    const float* R1    = (const float*)d_in[4];
    const float* b1    = (const float*)d_in[5];
    const float* Wc    = (const float*)d_in[6];
    const float* Rc    = (const float*)d_in[7];
    const float* bc    = (const float*)d_in[8];
    const float* l1w   = (const float*)d_in[9];
    const float* l1b   = (const float*)d_in[10];
    const float* l2w   = (const float*)d_in[11];
    const float* l2b   = (const float*)d_in[12];
    float* out     = (float*)d_out;
    float* lastOut = out + NG * NC;   // tuple order: (log_softmax, last)

    cudaFuncSetAttribute(k_mmagemm, cudaFuncAttributeMaxDynamicSharedMemorySize, SM2_TOTAL);

    // preprocessing: zero, then degree histogram (+ concurrent weight split)
    k_pre <<<196, 256>>>();
    k_deg <<<2352, 256>>>(ei, W1, R1, Wc, Rc);
    k_off <<<(NN + 255) / 256, 256>>>();
    k_fill<<<(NE + 255) / 256, 256>>>(ei);

    // 4 GCS layers; relu lives in k_agg; last agg writes fp32 lastOut
    int inSel = -1;
    int outSel = 0;
    for (int l = 0; l < 4; l++) {
        const float* b = (l == 0) ? b1 : bc + (l - 1) * HH;
        k_mmagemm<<<GEMM_GRID, 256, SM2_TOTAL>>>(x, inSel, outSel, l, b);
        k_agg<<<(NN + 3) / 4, 128>>>(outSel, (l == 3) ? 1 : 0, lastOut);
        inSel = outSel;
        outSel ^= 1;
    }

    k_pool<<<(NN + 63) / 64, 128>>>(lastOut, batch);
    k_head<<<NG, 128>>>(l1w, l1b, l2w, l2b, out);
}

// round 17
// speedup vs baseline: 1.5364x; 1.0265x over previous
#include <cuda_runtime.h>
#include <cuda_fp16.h>
#include <cstdint>

#define NN 50000
#define NE 600000
#define HH 128
#define NG 128
#define NC 10
#define NT64 782                    // ceil(50000/64)
#define GEMM_GRID 296               // 2 CTAs per SM, persistent

// ---------------- tile geometry ----------------------------------------------
#define TSTRIDE 272                 // 128 fp16 (256B) + 16B pad -> ldmatrix conflict-free
#define TILE_B  (128 * TSTRIDE)     // 34816 bytes per 128x128 fp16 image

// ---------------- scratch (static device globals; no allocation) ------------
__device__ __half g_h [NN*HH];     // W-path output, fp16
__device__ __half g_f0[NN*HH];     // activation ping (fp16, relu'd by agg)
__device__ __half g_f1[NN*HH];     // activation pong
__device__ uint2 g_edge[NE];       // packed {src, bits(w)} CSR records
__device__ int   g_deg [NN];       // zero at call entry (reset by tail of prev call)
__device__ int   g_beg [NN];       // after k_fill: END of each segment
__device__ int   g_total;          // zero at call entry
__device__ float g_dinv[NN];
__device__ float g_pool[NG*HH];    // zero at call entry
__device__ float g_cnt [NG];       // zero at call entry
// fp16 weight images: [layer][W,R][TILE_B] -- W,R contiguous per layer
__device__ __align__(16) char g_wimg[4][2][TILE_B];

__device__ __forceinline__ __half* selBuf(int s) { return s ? g_f1 : g_f0; }

__device__ __forceinline__ uint32_t s2u(const void* p) {
    uint32_t a;
    asm("{ .reg .u64 t; cvta.to.shared.u64 t, %1; cvt.u32.u64 %0, t; }"
        : "=r"(a) : "l"(p));
    return a;
}

// ---------------- GEMM SMEM layout (per CTA: 87040 B -> 2 CTA/SM) -----------
#define A16  0
#define BW16 17408                  // W image
#define BR16 (17408 + TILE_B)       // R image
#define SM2_TOTAL (17408 + 2 * TILE_B)   // 87040

__device__ __forceinline__ void ldm4(uint32_t* r, uint32_t addr) {
    asm volatile("ldmatrix.sync.aligned.m8n8.x4.shared.b16 {%0,%1,%2,%3}, [%4];"
                 : "=r"(r[0]), "=r"(r[1]), "=r"(r[2]), "=r"(r[3]) : "r"(addr));
}
__device__ __forceinline__ void mma16816h(float* c, const uint32_t* a,
                                          uint32_t b0, uint32_t b1) {
    asm volatile(
        "mma.sync.aligned.m16n8k16.row.col.f32.f16.f16.f32 "
        "{%0,%1,%2,%3}, {%4,%5,%6,%7}, {%8,%9}, {%0,%1,%2,%3};"
        : "+f"(c[0]), "+f"(c[1]), "+f"(c[2]), "+f"(c[3])
        : "r"(a[0]), "r"(a[1]), "r"(a[2]), "r"(a[3]), "r"(b0), "r"(b1));
}

__device__ __forceinline__ uint32_t packh2(float a, float b) {
    __half2 h = __floats2half2_rn(a, b);
    return *(uint32_t*)&h;
}

// ---------------- fp16 weight images (main stream, before layer-0 GEMM) -----
__global__ void k_split(const float* __restrict__ W1, const float* __restrict__ R1,
                        const float* __restrict__ Wc, const float* __restrict__ Rc) {
    const int layer = blockIdx.x >> 1;
    const int isR = blockIdx.x & 1;
    const float* src;
    if (layer == 0) src = isR ? R1 : W1;
    else src = (isR ? Rc : Wc) + (layer - 1) * HH * HH;
    char* img = g_wimg[layer][isR];
    for (int idx = threadIdx.x; idx < HH * HH; idx += 256) {
        int n = idx >> 7, k = idx & 127;
        __half h = __float2half(src[k * HH + n]);   // transpose [k][n] -> [n][k]
        *(unsigned short*)(img + n * TSTRIDE + k * 2) = *(unsigned short*)&h;
    }
}

// ---------------- degree histogram (side stream) -----------------------------
__global__ void k_deg(const int* __restrict__ ei) {
    int e = blockIdx.x * 256 + threadIdx.x;
    if (e < NE) {
        int d = ei[NE + e];
        if (d >= 0 && d < NN) atomicAdd(&g_deg[d], 1);
    }
}

// ---------------- CSR offsets (fused dinv + scan, side stream) ---------------
__global__ void k_off() {
    __shared__ int sh[256];
    __shared__ int base;
    const int t = threadIdx.x;
    const int i = blockIdx.x * 256 + t;
    int d = (i < NN) ? g_deg[i] : 0;
    if (i < NN) g_dinv[i] = (d > 0) ? rsqrtf((float)d) : 0.f;
    sh[t] = d;
    __syncthreads();
    for (int off = 1; off < 256; off <<= 1) {
        int v = (t >= off) ? sh[t - off] : 0;
        __syncthreads();
        sh[t] += v;
        __syncthreads();
    }
    if (t == 255) base = atomicAdd(&g_total, sh[255]);
    __syncthreads();
    if (i < NN) g_beg[i] = base + sh[t] - d;
}

// fill atomics run directly on g_beg; afterwards g_beg[i] == segment END
__global__ void k_fill(const int* __restrict__ ei) {
    int e = blockIdx.x * blockDim.x + threadIdx.x;
    if (e < NE) {
        int s = ei[e];
        int d = ei[NE + e];
        if (s < 0 || s >= NN || d < 0 || d >= NN) return;
        float w = g_dinv[s] * g_dinv[d];
        int pos = atomicAdd(&g_beg[d], 1);
        g_edge[pos] = make_uint2((uint32_t)s, __float_as_uint(w));
    }
}

// ---------------- persistent fused dual-output GEMM --------------------------
// one CTA per tile computes BOTH: g_h = X@W (fp16) and f16 = X@R + bias (fp16)
// X: layer 0 = external fp32 x (no relu); layers 1-3 = fp16 buffer (already relu'd)
__global__ void __launch_bounds__(256, 2) k_mmagemm(
    const float* __restrict__ Xext, int inSel, int outSel, int layer,
    const float* __restrict__ bias)
{
    extern __shared__ char smem[];
    const uint32_t sbase = s2u(smem);
    const int tid = threadIdx.x;
    const int wid = tid >> 5, lane = tid & 31;
    const __half* X16 = (inSel < 0) ? (const __half*)0 : selBuf(inSel);
    __half* dstF = selBuf(outSel);

    // ---- both B images (69632 B contiguous) loaded ONCE per CTA ----
    {
        const float4* src = (const float4*)g_wimg[layer][0];
        float4* d4 = (float4*)(smem + BW16);
#pragma unroll
        for (int it = 0; it < 17; it++)
            d4[it * 256 + tid] = src[it * 256 + tid];
    }

    // warp decomposition
    const int wm = wid & 1;
    const int wn = wid >> 1;           // 0..3
    const int n0 = wn * 32;
    const uint32_t aOff = (uint32_t)((wm * 32 + (lane & 15)) * TSTRIDE
                                     + (lane >> 4) * 16);
    const int q = lane >> 3, r8 = lane & 7;
    const uint32_t bOff = (uint32_t)((n0 + ((q & 2) << 2) + r8) * TSTRIDE
                                     + (q & 1) * 16);
    const uint32_t aB = sbase + A16;
    const uint32_t bWB = sbase + BW16, bRB = sbase + BR16;
    const int gq = lane >> 2, t4 = lane & 3;

    float bx[4], by[4];
#pragma unroll
    for (int nf = 0; nf < 4; nf++) {
        float2 bv = *(const float2*)(bias + n0 + nf * 8 + 2 * t4);
        bx[nf] = bv.x; by[nf] = bv.y;
    }

    const int lm = tid >> 5;           // fp32 A-load base row
    const int lc4 = (tid & 31) * 4;    // fp32 A-load col
    const int hm = tid >> 4;           // fp16 A-load: rows hm + it*16
    const int hc8 = (tid & 15) * 8;    // fp16 A-load col (8 halves = 16B)

    for (int tile = blockIdx.x; tile < NT64; tile += GEMM_GRID) {
        const int row0 = tile * 64;

        __syncthreads();   // previous mainloop done reading A
        if (inSel < 0) {
            // ---- layer 0: 64x128 fp32 -> fp16 ----
#pragma unroll
            for (int it = 0; it < 8; it++) {
                int gr = row0 + lm + it * 8;
                float4 w = (gr < NN) ? *(const float4*)(Xext + gr * 128 + lc4)
                                     : make_float4(0.f, 0.f, 0.f, 0.f);
                uint32_t bo = (lm + it * 8) * TSTRIDE + lc4 * 2;
                *(uint32_t*)(smem + A16 + bo)     = packh2(w.x, w.y);
                *(uint32_t*)(smem + A16 + bo + 4) = packh2(w.z, w.w);
            }
        } else {
            // ---- layers 1-3: straight fp16 16B copies ----
#pragma unroll
            for (int it = 0; it < 4; it++) {
                int m = hm + it * 16;
                int gr = row0 + m;
                uint4 w = (gr < NN) ? *(const uint4*)(X16 + gr * 128 + hc8)
                                    : make_uint4(0u, 0u, 0u, 0u);
                *(uint4*)(smem + A16 + m * TSTRIDE + hc8 * 2) = w;
            }
        }
        __syncthreads();

        float cW[2][4][4], cR[2][4][4];
#pragma unroll
        for (int i = 0; i < 2; i++)
#pragma unroll
            for (int j = 0; j < 4; j++)
#pragma unroll
                for (int z = 0; z < 4; z++) { cW[i][j][z] = 0.f; cR[i][j][z] = 0.f; }

#pragma unroll 1
        for (int k0 = 0; k0 < 128; k0 += 16) {
            const uint32_t kB = (uint32_t)(k0 * 2);
            uint32_t a[2][4];
#pragma unroll
            for (int mf = 0; mf < 2; mf++)
                ldm4(a[mf], aB + aOff + mf * (16 * TSTRIDE) + kB);
#pragma unroll
            for (int nf2 = 0; nf2 < 2; nf2++) {
                uint32_t bb[4];
                ldm4(bb, bWB + bOff + nf2 * (16 * TSTRIDE) + kB);
#pragma unroll
                for (int mf = 0; mf < 2; mf++) {
                    mma16816h(cW[mf][nf2 * 2],     a[mf], bb[0], bb[1]);
                    mma16816h(cW[mf][nf2 * 2 + 1], a[mf], bb[2], bb[3]);
                }
                ldm4(bb, bRB + bOff + nf2 * (16 * TSTRIDE) + kB);
#pragma unroll
                for (int mf = 0; mf < 2; mf++) {
                    mma16816h(cR[mf][nf2 * 2],     a[mf], bb[0], bb[1]);
                    mma16816h(cR[mf][nf2 * 2 + 1], a[mf], bb[2], bb[3]);
                }
            }
        }

        // ---- epilogue: W -> fp16 g_h ; R + bias -> fp16 f ----
#pragma unroll
        for (int nf = 0; nf < 4; nf++) {
            const int col = n0 + nf * 8 + 2 * t4;
#pragma unroll
            for (int mf = 0; mf < 2; mf++) {
                int rlo = row0 + wm * 32 + mf * 16 + gq;
                if (rlo < NN) {
                    *(__half2*)(g_h + rlo * 128 + col) =
                        __floats2half2_rn(cW[mf][nf][0], cW[mf][nf][1]);
                    *(__half2*)(dstF + rlo * 128 + col) =
                        __floats2half2_rn(cR[mf][nf][0] + bx[nf], cR[mf][nf][1] + by[nf]);
                }
                if (rlo + 8 < NN) {
                    *(__half2*)(g_h + (rlo + 8) * 128 + col) =
                        __floats2half2_rn(cW[mf][nf][2], cW[mf][nf][3]);
                    *(__half2*)(dstF + (rlo + 8) * 128 + col) =
                        __floats2half2_rn(cR[mf][nf][2] + bx[nf], cR[mf][nf][3] + by[nf]);
                }
            }
        }
    }
}

// ---------------- CSR aggregation: warp per node, fp16 gather ---------------
// relu applied here; non-last: write fp16 next-layer input; last: fp32 lastOut
__global__ void k_agg(int outSel, int last, float* __restrict__ lastOut) {
    __half* f = selBuf(outSel);
    const int wid = threadIdx.x >> 5, lane = threadIdx.x & 31;
    const int i = blockIdx.x * 4 + wid;
    if (i >= NN) return;
    const int end = g_beg[i];
    const int beg = end - g_deg[i];
    const int laneOff = lane * 4;
    // init: skip connection (fp16 f from GEMM) -> fp32
    float4 acc;
    {
        uint2 u = *(const uint2*)(f + i * HH + laneOff);
        float2 a = __half22float2(*(__half2*)&u.x), b = __half22float2(*(__half2*)&u.y);
        acc = make_float4(a.x, a.y, b.x, b.y);
    }
    int e = beg;
    for (; e + 4 <= end; e += 4) {
        uint2 e0 = g_edge[e],   e1 = g_edge[e+1];
        uint2 e2 = g_edge[e+2], e3 = g_edge[e+3];
        float w0 = __uint_as_float(e0.y), w1 = __uint_as_float(e1.y);
        float w2 = __uint_as_float(e2.y), w3 = __uint_as_float(e3.y);
        uint2 u0 = *(const uint2*)(g_h + e0.x * HH + laneOff);
        uint2 u1 = *(const uint2*)(g_h + e1.x * HH + laneOff);
        uint2 u2 = *(const uint2*)(g_h + e2.x * HH + laneOff);
        uint2 u3 = *(const uint2*)(g_h + e3.x * HH + laneOff);
        float2 a0 = __half22float2(*(__half2*)&u0.x), b0 = __half22float2(*(__half2*)&u0.y);
        float2 a1 = __half22float2(*(__half2*)&u1.x), b1 = __half22float2(*(__half2*)&u1.y);
        float2 a2 = __half22float2(*(__half2*)&u2.x), b2 = __half22float2(*(__half2*)&u2.y);
        float2 a3 = __half22float2(*(__half2*)&u3.x), b3 = __half22float2(*(__half2*)&u3.y);
        acc.x += a0.x*w0 + a1.x*w1 + a2.x*w2 + a3.x*w3;
        acc.y += a0.y*w0 + a1.y*w1 + a2.y*w2 + a3.y*w3;
        acc.z += b0.x*w0 + b1.x*w1 + b2.x*w2 + b3.x*w3;
        acc.w += b0.y*w0 + b1.y*w1 + b2.y*w2 + b3.y*w3;
    }
    for (; e < end; e++) {
        uint2 ed = g_edge[e];
        float w = __uint_as_float(ed.y);
        uint2 u = *(const uint2*)(g_h + ed.x * HH + laneOff);
        float2 a = __half22float2(*(__half2*)&u.x), b = __half22float2(*(__half2*)&u.y);
        acc.x += a.x * w; acc.y += a.y * w;
        acc.z += b.x * w; acc.w += b.y * w;
    }
    acc.x = fmaxf(acc.x, 0.f); acc.y = fmaxf(acc.y, 0.f);
    acc.z = fmaxf(acc.z, 0.f); acc.w = fmaxf(acc.w, 0.f);
    if (last) {
        *(float4*)(lastOut + i * HH + laneOff) = acc;
    } else {
        uint2 o;
        *(__half2*)&o.x = __floats2half2_rn(acc.x, acc.y);
        *(__half2*)&o.y = __floats2half2_rn(acc.z, acc.w);
        *(uint2*)(f + i * HH + laneOff) = o;
    }
}

// ---------------- mean-pool accumulation + state reset -----------------------
__global__ void k_pool(const float* __restrict__ f,
                       const int* __restrict__ batch) {
    const int t = threadIdx.x;
    const int base = blockIdx.x * 64;
    float acc = 0.f;
    int cur = -1;
    for (int r = 0; r < 64; r++) {
        int i = base + r;
        if (i >= NN) break;
        float v = f[i * HH + t];
        int bg = batch[i];
        if (bg != cur) {
            if (cur >= 0) atomicAdd(&g_pool[cur * HH + t], acc);
            cur = bg; acc = 0.f;
        }
        acc += v;
    }
    if (cur >= 0) atomicAdd(&g_pool[cur * HH + t], acc);
    if (t == 0) {
        int c = 0; int cb = -1;
        for (int r = 0; r < 64; r++) {
            int i = base + r;
            if (i >= NN) break;
            int bg = batch[i];
            if (bg != cb) {
                if (cb >= 0) atomicAdd(&g_cnt[cb], (float)c);
                cb = bg; c = 0;
            }
            c++;
        }
        if (cb >= 0) atomicAdd(&g_cnt[cb], (float)c);
    }
    // tail reset for next call (g_deg/g_total no longer needed this call)
    int gi = blockIdx.x * 128 + t;
    if (gi < NN) g_deg[gi] = 0;
    if (gi == 0) g_total = 0;
}

// ---------------- MLP head + log_softmax + pool reset ------------------------
__global__ void k_head(const float* __restrict__ l1w, const float* __restrict__ l1b,
                       const float* __restrict__ l2w, const float* __restrict__ l2b,
                       float* __restrict__ out) {
    __shared__ float p[HH];
    __shared__ float gg[HH];
    __shared__ float lg[NC];
    const int g = blockIdx.x, t = threadIdx.x;
    float c = fmaxf(g_cnt[g], 1.f);
    p[t] = g_pool[g * HH + t] / c;
    __syncthreads();
    // tail reset for next call (all threads have read g_pool/g_cnt above)
    g_pool[g * HH + t] = 0.f;
    if (t == 0) g_cnt[g] = 0.f;
    float a = l1b[t];
#pragma unroll 8
    for (int k = 0; k < HH; k++) a += p[k] * l1w[k * HH + t];
    gg[t] = fmaxf(a, 0.f);
    __syncthreads();
    if (t < NC) {
        float a2 = l2b[t];
        for (int k = 0; k < HH; k++) a2 += gg[k] * l2w[k * NC + t];
        lg[t] = a2;
    }
    __syncthreads();
    if (t < NC) {
        float m = lg[0];
        for (int j = 1; j < NC; j++) m = fmaxf(m, lg[j]);
        float s = 0.f;
        for (int j = 0; j < NC; j++) s += expf(lg[j] - m);
        out[g * NC + t] = lg[t] - m - logf(s);
    }
}

// ---------------- launch -----------------------------------------------------
extern "C" void kernel_launch(void* const* d_in, const int* in_sizes, int n_in,
                              void* d_out, int out_size) {
    const float* x     = (const float*)d_in[0];
    const int*   ei    = (const int*)d_in[1];
    const int*   batch = (const int*)d_in[2];
    const float* W1    = (const float*)d_in[3];
    const float* R1    = (const float*)d_in[4];
    const float* b1    = (const float*)d_in[5];
    const float* Wc    = (const float*)d_in[6];
    const float* Rc    = (const float*)d_in[7];
    const float* bc    = (const float*)d_in[8];
    const float* l1w   = (const float*)d_in[9];
    const float* l1b   = (const float*)d_in[10];
    const float* l2w   = (const float*)d_in[11];
    const float* l2b   = (const float*)d_in[12];
    float* out     = (float*)d_out;
    float* lastOut = out + NG * NC;   // tuple order: (log_softmax, last)

    cudaFuncSetAttribute(k_mmagemm, cudaFuncAttributeMaxDynamicSharedMemorySize, SM2_TOTAL);

    // fork: CSR build on side stream, layer-0 GEMM on main stream
    cudaStream_t s2;
    cudaStreamCreateWithFlags(&s2, cudaStreamNonBlocking);
    cudaEvent_t evF, evJ;
    cudaEventCreateWithFlags(&evF, cudaEventDisableTiming);
    cudaEventCreateWithFlags(&evJ, cudaEventDisableTiming);

    cudaEventRecord(evF, 0);
    cudaStreamWaitEvent(s2, evF, 0);
    k_deg <<<(NE + 255) / 256, 256, 0, s2>>>(ei);
    k_off <<<(NN + 255) / 256, 256, 0, s2>>>();
    k_fill<<<(NE + 255) / 256, 256, 0, s2>>>(ei);
    cudaEventRecord(evJ, s2);

    // main stream: weight images + layer-0 GEMM (independent of CSR)
    k_split<<<8, 256>>>(W1, R1, Wc, Rc);
    k_mmagemm<<<GEMM_GRID, 256, SM2_TOTAL>>>(x, -1, 0, 0, b1);

    // join: CSR ready before first aggregation
    cudaStreamWaitEvent(0, evJ, 0);
    k_agg<<<(NN + 3) / 4, 128>>>(0, 0, lastOut);

    // layers 1-3
    int inSel = 0, outSel = 1;
    for (int l = 1; l < 4; l++) {
        k_mmagemm<<<GEMM_GRID, 256, SM2_TOTAL>>>(x, inSel, outSel, l, bc + (l - 1) * HH);
        k_agg<<<(NN + 3) / 4, 128>>>(outSel, (l == 3) ? 1 : 0, lastOut);
        inSel = outSel;
        outSel ^= 1;
    }

    k_pool<<<(NN + 63) / 64, 128>>>(lastOut, batch);
    k_head<<<NG, 128>>>(l1w, l1b, l2w, l2b, out);
}